// round 6
// baseline (speedup 1.0000x reference)
#include <cuda_runtime.h>

// BicycleModel: B=65536 vehicles, 256 steps, 4 output planes [B,256] f32.
// R6: occupancy-focused rework of R5.
//  - 15.4KB smem/block (32-thread warp-blocks) -> 14 blocks/SM (was 8)
//  - state staging: 16-t double store phases, stride-5 float4, conflict-free
//  - control staging: single 16-t half buffer, restaged mid-chunk from regs
//  - LDG lane remap so prefetched float4s STS.128 directly; compute reads
//    controls via one LDS.128 per 4 steps
//  - __launch_bounds__(32,14) pins regs <= 146

constexpr int BV   = 65536;
constexpr int NS   = 256;
constexpr int BLK  = 32;
constexpr int NCH  = 8;            // chunks of 32 timesteps
constexpr int NF4  = NS / 4;       // 64 float4 per row
constexpr int CSTR = 5;            // ctrl row stride (float4), rows of 4 (+pad)
constexpr int SSTR = 5;            // state row stride (float4)

constexpr float DT        = 0.05f;
constexpr float MAX_STEER = 0.52359877559829887f;
constexpr float MAX_SPEED = 100.0f;
constexpr float INV_WB    = 1.0f / 2.7f;

__global__ __launch_bounds__(BLK, 14)
void bicycle_kernel(const float*  __restrict__ sx,
                    const float*  __restrict__ sy,
                    const float*  __restrict__ syaw,
                    const float*  __restrict__ ssp,
                    const float4* __restrict__ acc,
                    const float4* __restrict__ str,
                    float4*       __restrict__ out)
{
    __shared__ float4 ca4[32 * CSTR];        // acc   half-chunk [v][t4], 2560B
    __shared__ float4 cs4[32 * CSTR];        // steer half-chunk            2560B
    __shared__ float4 st4[4][32 * SSTR];     // x,y,yaw,sp half-chunk      10240B

    const int lane = threadIdx.x;
    const int lv   = lane & 7;               // vehicle-within-octet for ldg/sts
    const int lt   = lane >> 3;              // t4 slot (0..3)
    const int vb   = blockIdx.x * BLK;
    const int b    = vb + lane;

    float x   = sx[b];
    float y   = sy[b];
    float yaw = syaw[b];
    float sp  = ssp[b];

    const unsigned plane4 = (unsigned)BV * NF4;
    const float4* arow = acc + (unsigned)vb * NF4;
    const float4* srow = str + (unsigned)vb * NF4;
    float4*       orow = out + (unsigned)vb * NF4;

    float4 ra[4], rs[4];

    // Load one 16-t half: lane holds (v = it*8+lv, t4 = lt). Address set per
    // instruction = 8 vehicles x 64B contiguous -> fully coalesced.
#define LOADH(c, h)                                                          \
    _Pragma("unroll")                                                        \
    for (int it = 0; it < 4; ++it) {                                         \
        int v = it * 8 + lv;                                                 \
        unsigned g = (unsigned)v * NF4 + (unsigned)(c) * 8 + (h) * 4 + lt;   \
        ra[it] = arow[g];                                                    \
        rs[it] = srow[g];                                                    \
    }

    // Stage held half into ctrl buffer. STS.128 at 5v+lt: per 8-lane phase
    // lt is uniform and v spans 8 consecutive -> distinct mod 8, CF.
#define STAGEH()                                                             \
    _Pragma("unroll")                                                        \
    for (int it = 0; it < 4; ++it) {                                         \
        int o = (it * 8 + lv) * CSTR + lt;                                   \
        ca4[o] = ra[it];                                                     \
        cs4[o] = rs[it];                                                     \
    }

#define STEP(A, ST) do {                                                     \
        float fr   = fmaf(0.01f * sp, sp, 0.1f * sp);                        \
        float spn  = fminf(fmaxf(fmaf(DT, (A) - fr, sp), 0.0f), MAX_SPEED);  \
        float sc   = fminf(fmaxf((ST), -MAX_STEER), MAX_STEER);              \
        float angv = sp * __tanf(sc) * INV_WB;                               \
        float sn, cc;                                                        \
        __sincosf(yaw, &sn, &cc);                                            \
        x   = fmaf(sp * cc, DT, x);                                          \
        y   = fmaf(sp * sn, DT, y);                                          \
        yaw = fmaf(angv, DT, yaw);                                           \
        sp  = spn;                                                           \
    } while (0)

    // 16 steps: controls via LDS.128 (lane*5+q, CF), pre-step states buffered
    // per 4 steps and STS.128'd at lane*5+q (CF).
#define COMPUTEH()                                                           \
    _Pragma("unroll")                                                        \
    for (int q = 0; q < 4; ++q) {                                            \
        float4 A4 = ca4[lane * CSTR + q];                                    \
        float4 S4 = cs4[lane * CSTR + q];                                    \
        float4 X, Y, W, S;                                                   \
        X.x = x; Y.x = y; W.x = yaw; S.x = sp;  STEP(A4.x, S4.x);            \
        X.y = x; Y.y = y; W.y = yaw; S.y = sp;  STEP(A4.y, S4.y);            \
        X.z = x; Y.z = y; W.z = yaw; S.z = sp;  STEP(A4.z, S4.z);            \
        X.w = x; Y.w = y; W.w = yaw; S.w = sp;                               \
        int o = lane * SSTR + q;                                             \
        st4[0][o] = X; st4[1][o] = Y; st4[2][o] = W; st4[3][o] = S;          \
        STEP(A4.w, S4.w);                                                    \
    }

    // Store half: LDS.128 at (v=it*8+lv)*5+lt (CF: per phase lt uniform,
    // 5v distinct mod 8), then 4 coalesced STG.128 (8 vehicles x 64B each;
    // the two halves of each 128B line merge in L2).
#define STOREH(c, h)                                                         \
    _Pragma("unroll")                                                        \
    for (int it = 0; it < 4; ++it) {                                         \
        int v = it * 8 + lv;                                                 \
        int o = v * SSTR + lt;                                               \
        unsigned g = (unsigned)v * NF4 + (unsigned)(c) * 8 + (h) * 4 + lt;   \
        orow[g]              = st4[0][o];                                    \
        orow[plane4 + g]     = st4[1][o];                                    \
        orow[2 * plane4 + g] = st4[2][o];                                    \
        orow[3 * plane4 + g] = st4[3][o];                                    \
    }

    // Prologue: buffer <- (0,h0); regs <- (0,h1).
    LOADH(0, 0); STAGEH();
    LOADH(0, 1);
    __syncwarp();

    // Invariant entering chunk c: buffer = (c,h0), regs = (c,h1).
    for (int c = 0; c < NCH; ++c) {
        COMPUTEH();                          // steps 0..15 of chunk c
        __syncwarp();

        STOREH(c, 0);
        STAGEH();                            // buffer <- (c,h1)
        if (c + 1 < NCH) { LOADH(c + 1, 0); }    // regs <- (c+1,h0)
        __syncwarp();

        COMPUTEH();                          // steps 16..31 of chunk c
        __syncwarp();

        STOREH(c, 1);
        if (c + 1 < NCH) {
            STAGEH();                        // buffer <- (c+1,h0)
            LOADH(c + 1, 1);                 // regs <- (c+1,h1)
        }
        __syncwarp();
    }
#undef STOREH
#undef COMPUTEH
#undef STEP
#undef STAGEH
#undef LOADH
}

extern "C" void kernel_launch(void* const* d_in, const int* in_sizes, int n_in,
                              void* d_out, int out_size)
{
    (void)in_sizes; (void)n_in; (void)out_size;
    const float*  sx   = (const float*)d_in[0];
    const float*  sy   = (const float*)d_in[1];
    const float*  syaw = (const float*)d_in[2];
    const float*  ssp  = (const float*)d_in[3];
    const float4* acc  = (const float4*)d_in[4];
    const float4* str  = (const float4*)d_in[5];

    bicycle_kernel<<<BV / BLK, BLK>>>(sx, sy, syaw, ssp, acc, str, (float4*)d_out);
}

// round 7
// speedup vs baseline: 1.7983x; 1.7983x over previous
#include <cuda_runtime.h>
#include <cuda.h>
#include <cstdint>

// BicycleModel: B=65536 vehicles, 256 steps, 4 output planes [B,256] f32.
// R7: TMA for ALL global traffic (SM was L1-wavefront bound in R4-R6).
//  - controls: TMA 2D loads (SW128, 32x32 f32 tiles), double-buffered,
//    prefetched 2 chunks ahead on an mbarrier pair
//  - states: staged to SW128 per-plane smem tiles (conflict-free STS.128),
//    written by TMA 3D stores (bulk_group), double-buffered via wait_group.read
//  - 32-thread blocks, 49KB smem, 4 blocks/SM; warps never touch DRAM latency

constexpr int BV  = 65536;
constexpr int NS  = 256;
constexpr int BLK = 32;
constexpr int NCH = 8;                 // chunks of 32 timesteps
constexpr int TILE4 = 256;             // float4 per 32x32 f32 tile (4KB)

constexpr float DT        = 0.05f;
constexpr float MAX_STEER = 0.52359877559829887f;
constexpr float MAX_SPEED = 100.0f;
constexpr float INV_WB    = 1.0f / 2.7f;

// dyn smem: [pad to 1KB] ctrlA[2][256] f4 | ctrlS[2][256] f4 | state[2][4][256] f4
constexpr int SMEM_BYTES = 1024 + (512 + 512 + 2048) * 16;   // 50176

__device__ __forceinline__ uint32_t s2u(const void* p) {
    uint32_t a;
    asm("{ .reg .u64 t; cvta.to.shared.u64 t, %1; cvt.u32.u64 %0, t; }"
        : "=r"(a) : "l"(p));
    return a;
}

__global__ __launch_bounds__(BLK)
void bicycle_kernel(const __grid_constant__ CUtensorMap ta,   // acc  [B,256]
                    const __grid_constant__ CUtensorMap ts,   // steer[B,256]
                    const __grid_constant__ CUtensorMap to,   // out  [4,B,256]
                    const float* __restrict__ sx,
                    const float* __restrict__ sy,
                    const float* __restrict__ syaw,
                    const float* __restrict__ ssp)
{
    extern __shared__ char smem_raw[];
    __shared__ alignas(8) unsigned long long mb[2];

    char* base = (char*)(((uintptr_t)smem_raw + 1023) & ~(uintptr_t)1023);
    float4* cA = (float4*)base;              // 2 x 4KB control (accel)
    float4* cS = cA + 2 * TILE4;             // 2 x 4KB control (steer)
    float4* sT = cS + 2 * TILE4;             // 2 x 4 x 4KB state planes

    const int lane = threadIdx.x;
    const int vb   = blockIdx.x * BLK;
    const int b    = vb + lane;

    float x   = sx[b];
    float y   = sy[b];
    float yaw = syaw[b];
    float sp  = ssp[b];

    const uint32_t mb0 = s2u(&mb[0]);
    const uint32_t cAu = s2u(cA);
    const uint32_t cSu = s2u(cS);
    const uint32_t sTu = s2u(sT);

    if (lane == 0) {
        asm volatile("mbarrier.init.shared.b64 [%0], 1;" :: "r"(mb0) : "memory");
        asm volatile("mbarrier.init.shared.b64 [%0], 1;" :: "r"(mb0 + 8) : "memory");
        asm volatile("fence.proxy.async.shared::cta;" ::: "memory");
    }
    __syncwarp();

    // Issue TMA control loads for chunk cc into buffer cc&1.
#define ISSUE_LOAD(cc) do {                                                   \
        uint32_t mbar = mb0 + ((cc) & 1) * 8;                                 \
        uint32_t da = cAu + ((cc) & 1) * (TILE4 * 16);                        \
        uint32_t ds = cSu + ((cc) & 1) * (TILE4 * 16);                        \
        asm volatile("mbarrier.arrive.expect_tx.shared.b64 _, [%0], %1;"      \
                     :: "r"(mbar), "r"(8192u) : "memory");                    \
        asm volatile("cp.async.bulk.tensor.2d.shared::cta.global.tile"        \
                     ".mbarrier::complete_tx::bytes [%0], [%1, {%2, %3}], [%4];" \
                     :: "r"(da), "l"(&ta), "r"((cc) * 32), "r"(vb), "r"(mbar) \
                     : "memory");                                             \
        asm volatile("cp.async.bulk.tensor.2d.shared::cta.global.tile"        \
                     ".mbarrier::complete_tx::bytes [%0], [%1, {%2, %3}], [%4];" \
                     :: "r"(ds), "l"(&ts), "r"((cc) * 32), "r"(vb), "r"(mbar) \
                     : "memory");                                             \
    } while (0)

    if (lane == 0) { ISSUE_LOAD(0); ISSUE_LOAD(1); }

#define STEP(A, ST) do {                                                     \
        float fr   = fmaf(0.01f * sp, sp, 0.1f * sp);                        \
        float spn  = fminf(fmaxf(fmaf(DT, (A) - fr, sp), 0.0f), MAX_SPEED);  \
        float sc   = fminf(fmaxf((ST), -MAX_STEER), MAX_STEER);              \
        float angv = sp * __tanf(sc) * INV_WB;                               \
        float sn, cc2;                                                       \
        __sincosf(yaw, &sn, &cc2);                                           \
        x   = fmaf(sp * cc2, DT, x);                                         \
        y   = fmaf(sp * sn, DT, y);                                          \
        yaw = fmaf(angv, DT, yaw);                                           \
        sp  = spn;                                                           \
    } while (0)

    const int r8 = lane * 8;
    const int lx = lane & 7;

    for (int c = 0; c < NCH; ++c) {
        const int buf = c & 1;
        const int ph  = (c >> 1) & 1;

        // Wait for this chunk's control tiles (acquire).
        {
            uint32_t mbar = mb0 + buf * 8;
            uint32_t done;
            asm volatile("{\n\t.reg .pred p;\n\t"
                         "mbarrier.try_wait.parity.acquire.cta.shared::cta.b64 p, [%1], %2;\n\t"
                         "selp.b32 %0, 1, 0, p;\n\t}"
                         : "=r"(done) : "r"(mbar), "r"(ph) : "memory");
            if (!done) {
                asm volatile("{\n\t.reg .pred P1;\n\t"
                             "W%=:\n\t"
                             "mbarrier.try_wait.parity.acquire.cta.shared::cta.b64 P1, [%0], %1, 0x989680;\n\t"
                             "@P1 bra.uni D%=;\n\t"
                             "bra.uni W%=;\n\t"
                             "D%=:\n\t}"
                             :: "r"(mbar), "r"(ph) : "memory");
            }
        }

        // State buffer reuse: chunk c-2's TMA stores must be done READING smem.
        if (c >= 2) {
            if (lane == 0)
                asm volatile("cp.async.bulk.wait_group.read 1;" ::: "memory");
            __syncwarp();
        }

        // ---- Compute 32 steps; all smem ops SW128-swizzled, conflict-free ----
        const float4* A4p = cA + buf * TILE4;
        const float4* S4p = cS + buf * TILE4;
        float4* P0 = sT + (buf * 4 + 0) * TILE4;
        float4* P1 = sT + (buf * 4 + 1) * TILE4;
        float4* P2 = sT + (buf * 4 + 2) * TILE4;
        float4* P3 = sT + (buf * 4 + 3) * TILE4;

#pragma unroll
        for (int q = 0; q < 8; ++q) {
            const int si = r8 + (q ^ lx);           // SW128: col16 = q ^ (v&7)
            float4 A4 = A4p[si];
            float4 S4 = S4p[si];
            float4 X, Y, W, S;
            X.x = x; Y.x = y; W.x = yaw; S.x = sp;  STEP(A4.x, S4.x);
            X.y = x; Y.y = y; W.y = yaw; S.y = sp;  STEP(A4.y, S4.y);
            X.z = x; Y.z = y; W.z = yaw; S.z = sp;  STEP(A4.z, S4.z);
            X.w = x; Y.w = y; W.w = yaw; S.w = sp;  STEP(A4.w, S4.w);
            P0[si] = X; P1[si] = Y; P2[si] = W; P3[si] = S;
        }
        __syncwarp();

        // ---- Issue TMA stores for this chunk + control loads for c+2 ----
        if (lane == 0) {
            asm volatile("fence.proxy.async.shared::cta;" ::: "memory");
#pragma unroll
            for (int p = 0; p < 4; ++p) {
                uint32_t src = sTu + (buf * 4 + p) * (TILE4 * 16);
                asm volatile("cp.async.bulk.tensor.3d.global.shared::cta.tile.bulk_group"
                             " [%0, {%1, %2, %3}], [%4];"
                             :: "l"(&to), "r"(c * 32), "r"(vb), "r"(p), "r"(src)
                             : "memory");
            }
            asm volatile("cp.async.bulk.commit_group;" ::: "memory");
            if (c + 2 < NCH) ISSUE_LOAD(c + 2);
        }
        __syncwarp();
    }

    if (lane == 0)
        asm volatile("cp.async.bulk.wait_group 0;" ::: "memory");
#undef STEP
#undef ISSUE_LOAD
}

// ---------------- host ----------------

typedef CUresult (*EncodeFn)(CUtensorMap*, CUtensorMapDataType, cuuint32_t, void*,
                             const cuuint64_t*, const cuuint64_t*,
                             const cuuint32_t*, const cuuint32_t*,
                             CUtensorMapInterleave, CUtensorMapSwizzle,
                             CUtensorMapL2promotion, CUtensorMapFloatOOBfill);

extern "C" void kernel_launch(void* const* d_in, const int* in_sizes, int n_in,
                              void* d_out, int out_size)
{
    (void)in_sizes; (void)n_in; (void)out_size;

    void* fptr = nullptr;
    cudaDriverEntryPointQueryResult qr;
    cudaGetDriverEntryPointByVersion("cuTensorMapEncodeTiled", &fptr, 12000,
                                     cudaEnableDefault, &qr);
    EncodeFn encode = (EncodeFn)fptr;

    CUtensorMap ta, ts, to;

    // controls: [B, 256] f32, tile 32x32, SW128
    {
        cuuint64_t dims[2]    = {NS, BV};
        cuuint64_t strides[1] = {NS * 4};
        cuuint32_t box[2]     = {32, 32};
        cuuint32_t es[2]      = {1, 1};
        encode(&ta, CU_TENSOR_MAP_DATA_TYPE_FLOAT32, 2, d_in[4], dims, strides,
               box, es, CU_TENSOR_MAP_INTERLEAVE_NONE, CU_TENSOR_MAP_SWIZZLE_128B,
               CU_TENSOR_MAP_L2_PROMOTION_L2_128B, CU_TENSOR_MAP_FLOAT_OOB_FILL_NONE);
        encode(&ts, CU_TENSOR_MAP_DATA_TYPE_FLOAT32, 2, d_in[5], dims, strides,
               box, es, CU_TENSOR_MAP_INTERLEAVE_NONE, CU_TENSOR_MAP_SWIZZLE_128B,
               CU_TENSOR_MAP_L2_PROMOTION_L2_128B, CU_TENSOR_MAP_FLOAT_OOB_FILL_NONE);
    }
    // output: [4, B, 256] f32, tile 32x32x1, SW128
    {
        cuuint64_t dims[3]    = {NS, BV, 4};
        cuuint64_t strides[2] = {NS * 4, (cuuint64_t)BV * NS * 4};
        cuuint32_t box[3]     = {32, 32, 1};
        cuuint32_t es[3]      = {1, 1, 1};
        encode(&to, CU_TENSOR_MAP_DATA_TYPE_FLOAT32, 3, d_out, dims, strides,
               box, es, CU_TENSOR_MAP_INTERLEAVE_NONE, CU_TENSOR_MAP_SWIZZLE_128B,
               CU_TENSOR_MAP_L2_PROMOTION_L2_128B, CU_TENSOR_MAP_FLOAT_OOB_FILL_NONE);
    }

    cudaFuncSetAttribute(bicycle_kernel,
                         cudaFuncAttributeMaxDynamicSharedMemorySize, SMEM_BYTES);

    bicycle_kernel<<<BV / BLK, BLK, SMEM_BYTES>>>(
        ta, ts, to,
        (const float*)d_in[0], (const float*)d_in[1],
        (const float*)d_in[2], (const float*)d_in[3]);
}